// round 16
// baseline (speedup 1.0000x reference)
#include <cuda_runtime.h>
#include <cuda_fp16.h>
#include <cstdint>

#define F   16384
#define D   768
#define BSZ 512      // B*S
#define C   16
#define M   (F*C)

#define TI  64       // feature tile in scatter
#define TBS 128      // batch-seq tile in scatter

// Scratch (device globals — no allocations allowed)
__device__ __half g_udec_h[(size_t)F * D];     // up_decoder transposed, fp16: [F, D]
__device__ __half g_ufacts_h[(size_t)F * BSZ]; // up_facts transposed, fp16:   [F, BS]
__device__ float  g_values[M];

// ---------------------------------------------------------------------------
// Persistent pipelined transpose+convert, 64x32 source tiles:
// output-row segments are 64 halfs = 128B -> full-line DRAM writes.
//   tiles [0, 6144):   up_decoder [D, F]   -> g_udec_h   [F, D]   (12 x 512)
//   tiles [6144,10240): up_facts  [BSZ, F] -> g_ufacts_h [F, BSZ] ( 8 x 512)
// Double-buffered smem, one barrier/tile, next tile's LDGs issued before the
// current tile's convert/store phase. (Measured at the mixed R/W ceiling.)
// ---------------------------------------------------------------------------
#define T2_UDEC_TILES 6144
#define T2_TOT_TILES  10240
#define T2_GRID       1184

struct TileMeta {
    const float* src;
    __half*      dst;
    int rows, tx, ty;
};

__device__ __forceinline__ TileMeta decode_tile(int tt, const float* up_dec,
                                                const float* up_facts) {
    TileMeta m;
    if (tt < T2_UDEC_TILES) {
        m.src = up_dec;   m.dst = g_udec_h;   m.rows = D;
        m.ty = tt >> 9;   m.tx = tt & 511;
    } else {
        int t2 = tt - T2_UDEC_TILES;
        m.src = up_facts; m.dst = g_ufacts_h; m.rows = BSZ;
        m.ty = t2 >> 9;   m.tx = t2 & 511;
    }
    return m;
}

__global__ __launch_bounds__(256) void k_transpose_pipe(
        const float* __restrict__ up_dec, const float* __restrict__ up_facts) {
    __shared__ float buf[2][64][33];
    int lx = threadIdx.x, ly = threadIdx.y;   // ly == warp id (block 32x8)

    int tt = blockIdx.x;
    if (tt >= T2_TOT_TILES) return;

    TileMeta cur = decode_tile(tt, up_dec, up_facts);
    float v[8];
#pragma unroll
    for (int k = 0; k < 8; k++)
        v[k] = cur.src[(size_t)(cur.ty * 64 + ly + 8 * k) * F + cur.tx * 32 + lx];

    int p = 0;
    while (true) {
#pragma unroll
        for (int k = 0; k < 8; k++)
            buf[p][ly + 8 * k][lx] = v[k];

        int tn = tt + T2_GRID;
        __syncthreads();

        TileMeta nxt;
        float nv[8];
        bool have = (tn < T2_TOT_TILES);
        if (have) {
            nxt = decode_tile(tn, up_dec, up_facts);
#pragma unroll
            for (int k = 0; k < 8; k++)
                nv[k] = nxt.src[(size_t)(nxt.ty * 64 + ly + 8 * k) * F + nxt.tx * 32 + lx];
        }

        // Store phase: 4 output rows per warp, 32 lanes x half2 = 128B per row.
        {
            __half2* dsth2 = reinterpret_cast<__half2*>(cur.dst);
            int seg = cur.ty * 32;               // half2 offset within output row
            int rh2 = cur.rows >> 1;
#pragma unroll
            for (int k = 0; k < 4; k++) {
                int jj = ly + 8 * k;             // output row within tile (= src col)
                float a = buf[p][2 * lx + 0][jj];
                float b = buf[p][2 * lx + 1][jj];
                dsth2[(size_t)(cur.tx * 32 + jj) * rh2 + seg + lx] =
                    __floats2half2_rn(a, b);
            }
        }

        if (!have) break;
        p ^= 1;
        tt = tn;
        cur = nxt;
#pragma unroll
        for (int k = 0; k < 8; k++) v[k] = nv[k];
    }
}

// ---------------------------------------------------------------------------
// values[i*C+c] = down_encoder[i,:] . udec_h[j_ic,:]
// One warp per feature i, single-wave grid-stride. (At LTS cap.)
// ---------------------------------------------------------------------------
__global__ __launch_bounds__(256, 2) void k_values(const float* __restrict__ down_enc,
                                                   const int* __restrict__ j_idx) {
    int warp = threadIdx.x >> 5, lane = threadIdx.x & 31;
    int gw = blockIdx.x * 8 + warp;
    int nw = gridDim.x * 8;

    for (int i = gw; i < F; i += nw) {
        const float4* dr = reinterpret_cast<const float4*>(down_enc + (size_t)i * D);
        float4 dA[3], dB[3];
#pragma unroll
        for (int t = 0; t < 3; t++) {
            dA[t] = dr[t * 64 + lane * 2];
            dB[t] = dr[t * 64 + lane * 2 + 1];
        }
        int jl = 0;
        if (lane < C) jl = j_idx[i * C + lane];

        float acc[C];
#pragma unroll
        for (int c = 0; c < C; c++) acc[c] = 0.f;

#pragma unroll
        for (int g = 0; g < C; g += 4) {
            uint4 u[4][3];
#pragma unroll
            for (int q = 0; q < 4; q++) {
                int j = __shfl_sync(0xffffffffu, jl, g + q);
                const uint4* ur = reinterpret_cast<const uint4*>(g_udec_h + (size_t)j * D);
#pragma unroll
                for (int t = 0; t < 3; t++) u[q][t] = ur[t * 32 + lane];
            }
#pragma unroll
            for (int q = 0; q < 4; q++) {
                float a = acc[g + q];
#pragma unroll
                for (int t = 0; t < 3; t++) {
                    float2 f;
                    f = __half22float2(*reinterpret_cast<__half2*>(&u[q][t].x));
                    a = fmaf(f.x, dA[t].x, fmaf(f.y, dA[t].y, a));
                    f = __half22float2(*reinterpret_cast<__half2*>(&u[q][t].y));
                    a = fmaf(f.x, dA[t].z, fmaf(f.y, dA[t].w, a));
                    f = __half22float2(*reinterpret_cast<__half2*>(&u[q][t].z));
                    a = fmaf(f.x, dB[t].x, fmaf(f.y, dB[t].y, a));
                    f = __half22float2(*reinterpret_cast<__half2*>(&u[q][t].w));
                    a = fmaf(f.x, dB[t].z, fmaf(f.y, dB[t].w, a));
                }
                acc[g + q] = a;
            }
        }
#pragma unroll
        for (int c = 0; c < C; c++) {
#pragma unroll
            for (int o = 16; o; o >>= 1)
                acc[c] += __shfl_xor_sync(0xffffffffu, acc[c], o);
        }
#pragma unroll
        for (int c = 0; c < C; c++)
            if (lane == c) g_values[i * C + c] = acc[c];
    }
}

// ---------------------------------------------------------------------------
// Scatter: out[bs, i] = sum_c values[i*C+c] * ufacts_h[j[i*C+c], bs]
// (At gather floor.)
// ---------------------------------------------------------------------------
__global__ __launch_bounds__(256) void k_scatter(const int* __restrict__ j_idx,
                                                 float* __restrict__ out) {
    __shared__ float sacc[TI][TBS + 1];
    __shared__ float sval[TI * C];
    __shared__ int   sj[TI * C];

    int i0  = blockIdx.x * TI;
    int bs0 = blockIdx.y * TBS;
    int tid = threadIdx.x;

    for (int idx = tid; idx < TI * C; idx += 256) {
        sval[idx] = g_values[i0 * C + idx];
        sj[idx]   = j_idx[i0 * C + idx];
    }
    __syncthreads();

    int warp = tid >> 5, lane = tid & 31;
#pragma unroll 1
    for (int ii = warp * 8; ii < warp * 8 + 8; ii++) {
        float a0 = 0.f, a1 = 0.f, a2 = 0.f, a3 = 0.f;
#pragma unroll
        for (int c = 0; c < C; c++) {
            int   j = sj[ii * C + c];
            float v = sval[ii * C + c];
            uint2 u = *reinterpret_cast<const uint2*>(
                          g_ufacts_h + (size_t)j * BSZ + bs0 + lane * 4);
            float2 f;
            f = __half22float2(*reinterpret_cast<__half2*>(&u.x));
            a0 = fmaf(v, f.x, a0); a1 = fmaf(v, f.y, a1);
            f = __half22float2(*reinterpret_cast<__half2*>(&u.y));
            a2 = fmaf(v, f.x, a2); a3 = fmaf(v, f.y, a3);
        }
        sacc[ii][lane * 4 + 0] = a0;
        sacc[ii][lane * 4 + 1] = a1;
        sacc[ii][lane * 4 + 2] = a2;
        sacc[ii][lane * 4 + 3] = a3;
    }
    __syncthreads();

    for (int idx = tid; idx < TI * TBS; idx += 256) {
        int bs = idx >> 6;          // / TI
        int ii = idx & (TI - 1);
        out[(size_t)(bs0 + bs) * F + i0 + ii] = sacc[ii][bs];
    }
}

// ---------------------------------------------------------------------------
extern "C" void kernel_launch(void* const* d_in, const int* in_sizes, int n_in,
                              void* d_out, int out_size) {
    const float* up_facts = (const float*)d_in[0];  // [B,S,F]
    const float* down_enc = (const float*)d_in[1];  // [F, D]
    const float* up_dec   = (const float*)d_in[2];  // [D, F]
    const int*   j_idx    = (const int*)d_in[4];    // [M]
    float* out = (float*)d_out;                     // [B,S,F]

    dim3 tb(32, 8);
    k_transpose_pipe<<<T2_GRID, tb>>>(up_dec, up_facts);
    k_values<<<296, 256>>>(down_enc, j_idx);
    k_scatter<<<dim3(F / TI, BSZ / TBS), 256>>>(j_idx, out);
}